// round 15
// baseline (speedup 1.0000x reference)
#include <cuda_runtime.h>
#include <cuda_bf16.h>
#include <math.h>
#include <stdint.h>

// Problem constants
#define BT 4096
#define H  2048
#define V  32000

// GEMM tiling (int8: BK elems == BK bytes)
#define BM 128
#define BN 128
#define BK 128                  // K elems per stage (128 B per row)
#define NSTAGE 3
#define NK (H / BK)             // 16 K-chunks
#define NCH (V / BN)            // 250 vocab chunks
#define NTR (BT / BM)           // 32 token tiles
#define IGNORE_INDEX (-100)

// SMEM: 3 stages x (A 16KB + B 16KB) + bias/scale + partial arrays
#define STAGE_BYTES 32768
#define OFF_BIAS    (NSTAGE * STAGE_BYTES)          // 98304
#define OFF_SW      (OFF_BIAS + 512)
#define OFF_PM      (OFF_SW + 512)
#define OFF_PS      (OFF_PM + 4 * 128 * 4)
#define SMEM_DYN    (OFF_PS + 4 * 128 * 4)          // 103424

// ------------------------- device scratch (allocation-free) -----------------
__device__ int8_t g_xq[(size_t)BT * H];             // 8 MB
__device__ int8_t g_wq[(size_t)V * H];              // 64 MB
__device__ float  g_sx[BT];                         // per-token scale
__device__ float  g_sw[V];                          // per-vocab-row scale
__device__ float  g_pm[NCH * BT];
__device__ float  g_ps[NCH * BT];
__device__ float  g_tgt[BT];
__device__ float  g_sum;
__device__ int    g_cnt;
__device__ int    g_t64;

// ------------------------- small asm helpers --------------------------------
__device__ __forceinline__ uint32_t smem_u32(const void* p) {
    uint32_t a;
    asm("{ .reg .u64 t; cvta.to.shared.u64 t, %1; cvt.u32.u64 %0, t; }"
        : "=r"(a) : "l"(p));
    return a;
}

__device__ __forceinline__ void cp_async16(uint32_t saddr, const void* gaddr) {
    asm volatile("cp.async.cg.shared.global [%0], [%1], 16;"
                 :: "r"(saddr), "l"(gaddr) : "memory");
}
__device__ __forceinline__ void cp_commit() {
    asm volatile("cp.async.commit_group;" ::: "memory");
}
template <int N>
__device__ __forceinline__ void cp_wait() {
    asm volatile("cp.async.wait_group %0;" :: "n"(N) : "memory");
}

__device__ __forceinline__ void ldm_x4(uint32_t* r, uint32_t addr) {
    asm volatile("ldmatrix.sync.aligned.m8n8.x4.shared.b16 {%0,%1,%2,%3}, [%4];"
                 : "=r"(r[0]), "=r"(r[1]), "=r"(r[2]), "=r"(r[3]) : "r"(addr));
}

// int8 IMMA: m16n8k32, s8 x s8 -> s32. Byte layout of frags matches the
// bf16 m16n8k16 mapping exactly (4 consecutive k-bytes per register).
__device__ __forceinline__ void mma_s8(int* d, const uint32_t* a,
                                       uint32_t b0, uint32_t b1) {
    asm volatile(
        "mma.sync.aligned.m16n8k32.row.col.s32.s8.s8.s32 "
        "{%0,%1,%2,%3}, {%4,%5,%6,%7}, {%8,%9}, {%0,%1,%2,%3};"
        : "+r"(d[0]), "+r"(d[1]), "+r"(d[2]), "+r"(d[3])
        : "r"(a[0]), "r"(a[1]), "r"(a[2]), "r"(a[3]), "r"(b0), "r"(b1));
}

// ------------------------- target dtype handling ----------------------------
__device__ __forceinline__ long long load_target(const void* tp, int t) {
    const int* p32 = (const int*)tp;
    if (g_t64) {
        long long lo = (long long)(unsigned int)p32[2 * t];
        long long hi = (long long)p32[2 * t + 1];
        return lo | (hi << 32);
    }
    return (long long)p32[t];
}

__global__ void init_kernel(const void* target_raw) {
    __shared__ int any_odd;
    if (threadIdx.x == 0) any_odd = 0;
    __syncthreads();
    const int* p32 = (const int*)target_raw;
    int local = 0;
    for (int i = threadIdx.x; i < BT / 2; i += blockDim.x)
        if (p32[2 * i + 1] != 0) local = 1;
    if (local) atomicOr(&any_odd, 1);
    __syncthreads();
    if (threadIdx.x == 0) {
        g_t64 = any_odd ? 0 : 1;
        g_sum = 0.0f;
        g_cnt = 0;
    }
}

// ------------------------- fp32 -> int8 row quantization --------------------
// One block per row (2048 cols). Symmetric per-row scale = absmax/127,
// round-to-nearest. Row stays in registers between the two passes.
__global__ __launch_bounds__(256)
void quant_rows_kernel(const float* __restrict__ src, int8_t* __restrict__ dst,
                       float* __restrict__ scales)
{
    __shared__ float red[8];
    __shared__ float s_inv, s_scale;
    const int row = blockIdx.x;
    const int tid = threadIdx.x;

    const float4* s4 = (const float4*)(src + (size_t)row * H);
    float4 v0 = s4[tid * 2];
    float4 v1 = s4[tid * 2 + 1];
    float e[8] = {v0.x, v0.y, v0.z, v0.w, v1.x, v1.y, v1.z, v1.w};

    float amax = 0.0f;
    #pragma unroll
    for (int i = 0; i < 8; i++) amax = fmaxf(amax, fabsf(e[i]));
    #pragma unroll
    for (int off = 16; off >= 1; off >>= 1)
        amax = fmaxf(amax, __shfl_xor_sync(0xffffffffu, amax, off));
    if ((tid & 31) == 0) red[tid >> 5] = amax;
    __syncthreads();
    if (tid == 0) {
        float a = red[0];
        #pragma unroll
        for (int w = 1; w < 8; w++) a = fmaxf(a, red[w]);
        a = fmaxf(a, 1e-20f);
        s_scale = a / 127.0f;
        s_inv   = 127.0f / a;
        scales[row] = s_scale;
    }
    __syncthreads();

    const float inv = s_inv;
    uint32_t pk[2];
    #pragma unroll
    for (int h = 0; h < 2; h++) {
        uint32_t p = 0;
        #pragma unroll
        for (int i = 0; i < 4; i++) {
            int q = __float2int_rn(e[h * 4 + i] * inv);
            q = max(-127, min(127, q));
            p |= ((uint32_t)(q & 0xff)) << (i * 8);
        }
        pk[h] = p;
    }
    ((uint2*)(dst + (size_t)row * H))[tid] = make_uint2(pk[0], pk[1]);
}

// ------------------------- main GEMM + partial-LSE kernel -------------------
// CTA: 128 tokens x 128 vocab. 8 warps = 2(m) x 4(n); warp tile 64x32.
// mma.sync m16n8k32 s8, cp.async 3-stage pipeline, swizzled smem.
// Same byte-level layout as the bf16 version (rows are 128 B either way).
__global__ __launch_bounds__(256, 2)
void gemm_kernel(const void* __restrict__ target_raw,
                 const float* __restrict__ bias)
{
    extern __shared__ char smem[];
    const uint32_t sb = smem_u32(smem);

    const int tid  = threadIdx.x;
    const int wid  = tid >> 5;
    const int lane = tid & 31;
    const int wm   = wid >> 2;        // 0..1 : token half
    const int wn   = wid & 3;         // 0..3 : vocab quarter
    const int trow = blockIdx.x;
    const int chnk = blockIdx.y;
    const int row0 = trow * BM;
    const int col0 = chnk * BN;

    // bias + W-scale tiles -> smem
    float* sbias = (float*)(smem + OFF_BIAS);
    float* ssw   = (float*)(smem + OFF_SW);
    if (tid < 128) {
        sbias[tid] = bias[col0 + tid];
        ssw[tid]   = g_sw[col0 + tid];
    }

    // Cooperative-load addressing (constant offsets):
    // r = (tid>>3) + 32q, c = tid&7; global q-stride = 32*H bytes,
    // smem q-stride = 4096 B; advance +BK bytes per K-chunk.
    const int r0q = tid >> 3;
    const int c0q = tid & 7;
    const char* gAt = (const char*)(g_xq + (size_t)(row0 + r0q) * H) + c0q * 16;
    const char* gWt = (const char*)(g_wq + (size_t)(col0 + r0q) * H) + c0q * 16;
    const uint32_t st0 = (uint32_t)(r0q * 128 + ((c0q ^ (r0q & 7)) << 4));

    auto issue_loads = [&](int kchunk, int slot) {
        const uint32_t aB = sb + (uint32_t)slot * STAGE_BYTES + st0;
        const uint32_t bB = aB + 16384u;
        const char* pa = gAt + kchunk * BK;
        const char* pb = gWt + kchunk * BK;
        #pragma unroll
        for (int q = 0; q < 4; q++) {
            cp_async16(aB + q * 4096u, pa + q * (32 * H));
            cp_async16(bB + q * 4096u, pb + q * (32 * H));
        }
    };

    // ldmatrix addressing: identical to bf16 version (16B-chunk granularity).
    const int l7      = lane & 7;
    const int kc_lane = lane >> 4;
    const uint32_t arowbase = (uint32_t)((wm * 64 + (lane & 15)) * 128);
    const uint32_t browbase = (uint32_t)((wn * 32 + (lane & 15)) * 128);

    int acc[4][4][4];                 // [mt][nt][frag] int32
    #pragma unroll
    for (int i = 0; i < 4; i++)
        #pragma unroll
        for (int j = 0; j < 4; j++)
            #pragma unroll
            for (int c = 0; c < 4; c++)
                acc[i][j][c] = 0;

    // pipeline prologue
    issue_loads(0, 0); cp_commit();
    issue_loads(1, 1); cp_commit();

    for (int ki = 0; ki < NK; ki++) {
        cp_wait<1>();
        __syncthreads();

        if (ki + 2 < NK) issue_loads(ki + 2, (ki + 2) % NSTAGE);
        cp_commit();

        const uint32_t aBase = sb + (uint32_t)(ki % NSTAGE) * STAGE_BYTES;
        const uint32_t bBase = aBase + 16384u;

        #pragma unroll
        for (int ks = 0; ks < 4; ks++) {          // four k32 steps in BK=128
            const uint32_t ch = (uint32_t)(((ks * 2 + kc_lane) ^ l7) << 4);
            uint32_t af[4][4], bf[2][4];
            const uint32_t aAddr = aBase + arowbase + ch;
            ldm_x4(af[0], aAddr);
            ldm_x4(af[1], aAddr + 2048u);
            ldm_x4(af[2], aAddr + 4096u);
            ldm_x4(af[3], aAddr + 6144u);
            const uint32_t bAddr = bBase + browbase + ch;
            ldm_x4(bf[0], bAddr);
            ldm_x4(bf[1], bAddr + 2048u);
            #pragma unroll
            for (int mt = 0; mt < 4; mt++) {
                #pragma unroll
                for (int nt = 0; nt < 4; nt++) {
                    const int ng = nt >> 1, hh = nt & 1;
                    mma_s8(acc[mt][nt], af[mt], bf[ng][hh], bf[ng][hh + 2]);
                }
            }
        }
        // no trailing barrier: loads at iter ki target slot (ki-1)%3, whose
        // readers all passed this iteration's top barrier
    }

    // ---- epilogue: dequant, bias, target capture, per-row (m,s) -----------
    const int g  = lane >> 2;
    const int tc = lane & 3;

    float bv[4][2], wv[4][2];
    #pragma unroll
    for (int nt = 0; nt < 4; nt++) {
        const int cl = wn * 32 + nt * 8 + tc * 2;
        bv[nt][0] = sbias[cl];
        bv[nt][1] = sbias[cl + 1];
        wv[nt][0] = ssw[cl];
        wv[nt][1] = ssw[cl + 1];
    }

    float* spm = (float*)(smem + OFF_PM);   // [4][128]
    float* sps = (float*)(smem + OFF_PS);

    #pragma unroll
    for (int mt = 0; mt < 4; mt++) {
        #pragma unroll
        for (int hh = 0; hh < 2; hh++) {
            const int rloc = wm * 64 + mt * 16 + g + 8 * hh;
            const int t = row0 + rloc;
            const long long tg = load_target(target_raw, t);
            const float sx = g_sx[t];

            float v[8];
            float m = -INFINITY;
            #pragma unroll
            for (int nt = 0; nt < 4; nt++) {
                #pragma unroll
                for (int cc = 0; cc < 2; cc++) {
                    const float val = fmaf((float)acc[mt][nt][hh * 2 + cc],
                                           sx * wv[nt][cc], bv[nt][cc]);
                    v[nt * 2 + cc] = val;
                    m = fmaxf(m, val);
                    const long long cg = (long long)(col0 + wn * 32 + nt * 8 + tc * 2 + cc);
                    if (cg == tg) g_tgt[t] = val;
                }
            }
            float s = 0.0f;
            #pragma unroll
            for (int j = 0; j < 8; j++)
                s += __expf(v[j] - m);

            // reduce across the 4 lanes of the quad (same row)
            #pragma unroll
            for (int off = 1; off <= 2; off <<= 1) {
                float m2 = __shfl_xor_sync(0xffffffffu, m, off);
                float s2 = __shfl_xor_sync(0xffffffffu, s, off);
                float mn = fmaxf(m, m2);
                s = s * __expf(m - mn) + s2 * __expf(m2 - mn);
                m = mn;
            }
            if (tc == 0) {
                spm[wn * 128 + rloc] = m;
                sps[wn * 128 + rloc] = s;
            }
        }
    }
    __syncthreads();

    // merge 4 warp-column partials per row -> global partials
    if (tid < 128) {
        float m = spm[tid], s = sps[tid];
        #pragma unroll
        for (int w = 1; w < 4; w++) {
            float m2 = spm[w * 128 + tid];
            float s2 = sps[w * 128 + tid];
            float mn = fmaxf(m, m2);
            s = s * __expf(m - mn) + s2 * __expf(m2 - mn);
            m = mn;
        }
        g_pm[chnk * BT + row0 + tid] = m;
        g_ps[chnk * BT + row0 + tid] = s;
    }
}

// ------------------------- stage 2: merge + reduce --------------------------
__global__ __launch_bounds__(256)
void reduce_kernel(const void* __restrict__ target_raw)
{
    const int t = blockIdx.x * blockDim.x + threadIdx.x;

    float m = -INFINITY, s = 0.0f;
    for (int c = 0; c < NCH; c++) {
        float mc = g_pm[c * BT + t];
        float sc = g_ps[c * BT + t];
        float mn = fmaxf(m, mc);
        s = s * expf(m - mn) + sc * expf(mc - mn);
        m = mn;
    }
    const float lse = m + logf(s);

    const long long tg = load_target(target_raw, t);
    const int valid = (tg != (long long)IGNORE_INDEX) ? 1 : 0;
    float per = valid ? (lse - g_tgt[t]) : 0.0f;

    #pragma unroll
    for (int off = 16; off >= 1; off >>= 1)
        per += __shfl_xor_sync(0xffffffffu, per, off);
    int vc = valid;
    #pragma unroll
    for (int off = 16; off >= 1; off >>= 1)
        vc += __shfl_xor_sync(0xffffffffu, vc, off);
    if ((threadIdx.x & 31) == 0) {
        atomicAdd(&g_sum, per);
        atomicAdd(&g_cnt, vc);
    }
}

__global__ void finalize_kernel(float* __restrict__ out)
{
    int c = g_cnt;
    if (c < 1) c = 1;
    out[0] = g_sum / (float)c;
}

// ------------------------- host launch --------------------------------------
extern "C" void kernel_launch(void* const* d_in, const int* in_sizes, int n_in,
                              void* d_out, int out_size)
{
    const float* x          = (const float*)d_in[0];
    const void*  target_raw = d_in[1];
    const float* w          = (const float*)d_in[2];
    const float* bias       = (const float*)d_in[3];
    float*       out        = (float*)d_out;

    cudaFuncSetAttribute(gemm_kernel, cudaFuncAttributeMaxDynamicSharedMemorySize,
                         SMEM_DYN);

    void *xq = nullptr, *wq = nullptr, *sx = nullptr, *sw = nullptr;
    cudaGetSymbolAddress(&xq, g_xq);
    cudaGetSymbolAddress(&wq, g_wq);
    cudaGetSymbolAddress(&sx, g_sx);
    cudaGetSymbolAddress(&sw, g_sw);

    quant_rows_kernel<<<BT, 256>>>(x, (int8_t*)xq, (float*)sx);
    quant_rows_kernel<<<V, 256>>>(w, (int8_t*)wq, (float*)sw);

    init_kernel<<<1, 256>>>(target_raw);

    dim3 grid(NTR, NCH);
    gemm_kernel<<<grid, 256, SMEM_DYN>>>(target_raw, bias);

    reduce_kernel<<<BT / 256, 256>>>(target_raw);
    finalize_kernel<<<1, 1>>>(out);
}

// round 17
// speedup vs baseline: 1.7150x; 1.7150x over previous
#include <cuda_runtime.h>
#include <cuda_bf16.h>
#include <math.h>
#include <stdint.h>

// Problem constants
#define BT 4096
#define H  2048
#define V  32000

// GEMM tiling
#define BM 128
#define BN 128
#define BK 64                   // K elems per stage (128 B of bf16 per row)
#define NSTAGE 3
#define NK (H / BK)             // 32 K-chunks
#define NCH (V / BN)            // 250 vocab chunks
#define NTR (BT / BM)           // 32 token tiles
#define IGNORE_INDEX (-100)

// SMEM: 3 stages x (A 16KB + B 16KB) + bias + partial arrays + mbarriers
#define STAGE_BYTES 32768
#define OFF_BIAS    (NSTAGE * STAGE_BYTES)          // 98304
#define OFF_PM      (OFF_BIAS + 512)
#define OFF_PS      (OFF_PM + 4 * 128 * 4)
#define OFF_MBAR    (OFF_PS + 4 * 128 * 4)          // 6 mbarriers (full/empty x3)
#define SMEM_DYN    (OFF_MBAR + 64)

// ------------------------- device scratch (allocation-free) -----------------
__device__ __nv_bfloat16 g_xb[(size_t)BT * H];      // 16 MB
__device__ __nv_bfloat16 g_wb[(size_t)V * H];       // 128 MB
__device__ float g_pm[NCH * BT];
__device__ float g_ps[NCH * BT];
__device__ float g_tgt[BT];
__device__ float g_sum;
__device__ int   g_cnt;
__device__ int   g_t64;

// ------------------------- small asm helpers --------------------------------
__device__ __forceinline__ uint32_t smem_u32(const void* p) {
    uint32_t a;
    asm("{ .reg .u64 t; cvta.to.shared.u64 t, %1; cvt.u32.u64 %0, t; }"
        : "=r"(a) : "l"(p));
    return a;
}

__device__ __forceinline__ void cp_async16(uint32_t saddr, const void* gaddr) {
    asm volatile("cp.async.cg.shared.global [%0], [%1], 16;"
                 :: "r"(saddr), "l"(gaddr) : "memory");
}

// cp.async completion auto-arrives on mbarrier (one arrival per thread)
__device__ __forceinline__ void cp_async_arrive(uint32_t mbar) {
    asm volatile("cp.async.mbarrier.arrive.noinc.shared.b64 [%0];"
                 :: "r"(mbar) : "memory");
}

__device__ __forceinline__ void mbar_init(uint32_t mbar, uint32_t cnt) {
    asm volatile("mbarrier.init.shared.b64 [%0], %1;"
                 :: "r"(mbar), "r"(cnt) : "memory");
}

__device__ __forceinline__ void mbar_arrive(uint32_t mbar) {
    asm volatile("mbarrier.arrive.shared.b64 _, [%0];"
                 :: "r"(mbar) : "memory");
}

__device__ __forceinline__ void mbar_wait(uint32_t mbar, uint32_t parity) {
    asm volatile(
        "{\n\t.reg .pred P;\n\t"
        "W_%=:\n\t"
        "mbarrier.try_wait.parity.acquire.cta.shared::cta.b64 P, [%0], %1, 0x989680;\n\t"
        "@P bra.uni D_%=;\n\t"
        "bra.uni W_%=;\n\t"
        "D_%=:\n\t}"
        :: "r"(mbar), "r"(parity) : "memory");
}

__device__ __forceinline__ void ldm_x4(uint32_t* r, uint32_t addr) {
    asm volatile("ldmatrix.sync.aligned.m8n8.x4.shared.b16 {%0,%1,%2,%3}, [%4];"
                 : "=r"(r[0]), "=r"(r[1]), "=r"(r[2]), "=r"(r[3]) : "r"(addr));
}

__device__ __forceinline__ void mma_bf16(float* d, const uint32_t* a,
                                         uint32_t b0, uint32_t b1) {
    asm volatile(
        "mma.sync.aligned.m16n8k16.row.col.f32.bf16.bf16.f32 "
        "{%0,%1,%2,%3}, {%4,%5,%6,%7}, {%8,%9}, {%0,%1,%2,%3};"
        : "+f"(d[0]), "+f"(d[1]), "+f"(d[2]), "+f"(d[3])
        : "r"(a[0]), "r"(a[1]), "r"(a[2]), "r"(a[3]), "r"(b0), "r"(b1));
}

// ------------------------- target dtype handling ----------------------------
__device__ __forceinline__ long long load_target(const void* tp, int t) {
    const int* p32 = (const int*)tp;
    if (g_t64) {
        long long lo = (long long)(unsigned int)p32[2 * t];
        long long hi = (long long)p32[2 * t + 1];
        return lo | (hi << 32);
    }
    return (long long)p32[t];
}

__global__ void init_kernel(const void* target_raw) {
    __shared__ int any_odd;
    if (threadIdx.x == 0) any_odd = 0;
    __syncthreads();
    const int* p32 = (const int*)target_raw;
    int local = 0;
    for (int i = threadIdx.x; i < BT / 2; i += blockDim.x)
        if (p32[2 * i + 1] != 0) local = 1;
    if (local) atomicOr(&any_odd, 1);
    __syncthreads();
    if (threadIdx.x == 0) {
        g_t64 = any_odd ? 0 : 1;
        g_sum = 0.0f;
        g_cnt = 0;
    }
}

// ------------------------- fp32 -> bf16 conversion --------------------------
__global__ __launch_bounds__(256)
void convert_kernel(const float* __restrict__ src, __nv_bfloat16* __restrict__ dst, int n8)
{
    int i = blockIdx.x * blockDim.x + threadIdx.x;
    if (i >= n8) return;
    const float4* s4 = (const float4*)src;
    float4 a = s4[2 * i];
    float4 b = s4[2 * i + 1];
    __nv_bfloat162 p0 = __float22bfloat162_rn(make_float2(a.x, a.y));
    __nv_bfloat162 p1 = __float22bfloat162_rn(make_float2(a.z, a.w));
    __nv_bfloat162 p2 = __float22bfloat162_rn(make_float2(b.x, b.y));
    __nv_bfloat162 p3 = __float22bfloat162_rn(make_float2(b.z, b.w));
    uint4 o;
    o.x = *(const uint32_t*)&p0;
    o.y = *(const uint32_t*)&p1;
    o.z = *(const uint32_t*)&p2;
    o.w = *(const uint32_t*)&p3;
    ((uint4*)dst)[i] = o;
}

// ------------------------- main GEMM + partial-LSE kernel -------------------
// CTA: 128 tokens x 128 vocab. 8 warps = 2(m) x 4(n); warp tile 64x32.
// mma.sync m16n8k16 bf16, cp.async 3-stage pipeline with DECOUPLED mbarrier
// sync: full[s] (256 auto-arrivals from cp.async), empty[s] (8 warp arrivals).
// No __syncthreads in the mainloop -> warps skew and overlap LDSM with HMMA.
__global__ __launch_bounds__(256, 2)
void gemm_kernel(const void* __restrict__ target_raw,
                 const float* __restrict__ bias)
{
    extern __shared__ char smem[];
    const uint32_t sb = smem_u32(smem);
    const uint32_t mbF = sb + OFF_MBAR;        // full[s]  at mbF + s*16
    const uint32_t mbE = sb + OFF_MBAR + 8;    // empty[s] at mbE + s*16

    const int tid  = threadIdx.x;
    const int wid  = tid >> 5;
    const int lane = tid & 31;
    const int wm   = wid >> 2;        // 0..1 : token half
    const int wn   = wid & 3;         // 0..3 : vocab quarter
    const int trow = blockIdx.x;
    const int chnk = blockIdx.y;
    const int row0 = trow * BM;
    const int col0 = chnk * BN;

    // mbarrier init
    if (tid == 0) {
        #pragma unroll
        for (int s = 0; s < NSTAGE; s++) {
            mbar_init(mbF + s * 16u, 256);  // all threads' cp.async arrivals
            mbar_init(mbE + s * 16u, 8);    // one arrival per warp
        }
    }
    // bias tile -> smem (visible to epilogue via post-loop barrier)
    float* sbias = (float*)(smem + OFF_BIAS);
    if (tid < 128) sbias[tid] = bias[col0 + tid];
    __syncthreads();   // mbarriers initialized before any use

    // Cooperative-load addressing (constant offsets):
    // r = (tid>>3) + 32q, c = tid&7; global q-stride = 32*H*2 B,
    // smem q-stride = 4096 B; advance +128 B per K-chunk.
    const int r0q = tid >> 3;
    const int c0q = tid & 7;
    const char* gAt = (const char*)(g_xb + (size_t)(row0 + r0q) * H) + c0q * 16;
    const char* gWt = (const char*)(g_wb + (size_t)(col0 + r0q) * H) + c0q * 16;
    const uint32_t st0 = (uint32_t)(r0q * 128 + ((c0q ^ (r0q & 7)) << 4));

    auto produce = [&](int kchunk, int slot) {
        const uint32_t aB = sb + (uint32_t)slot * STAGE_BYTES + st0;
        const uint32_t bB = aB + 16384u;
        const char* pa = gAt + kchunk * (BK * 2);
        const char* pb = gWt + kchunk * (BK * 2);
        #pragma unroll
        for (int q = 0; q < 4; q++) {
            cp_async16(aB + q * 4096u, pa + q * (32 * H * 2));
            cp_async16(bB + q * 4096u, pb + q * (32 * H * 2));
        }
        cp_async_arrive(mbF + (uint32_t)slot * 16u);
    };

    // ldmatrix addressing (constant offsets; shared swizzle term)
    const int l7      = lane & 7;
    const int kc_lane = lane >> 4;
    const uint32_t arowbase = (uint32_t)((wm * 64 + (lane & 15)) * 128);
    const uint32_t browbase = (uint32_t)((wn * 32 + (lane & 15)) * 128);

    float acc[4][4][4];               // [mt][nt][frag]
    #pragma unroll
    for (int i = 0; i < 4; i++)
        #pragma unroll
        for (int j = 0; j < 4; j++)
            #pragma unroll
            for (int c = 0; c < 4; c++)
                acc[i][j][c] = 0.0f;

    // prologue: fill stages 0,1 (first use of each slot -> no empty wait)
    produce(0, 0);
    produce(1, 1);

    // consumer counters: slot cs, use-parity cup (use = ki/3)
    int cs = 0;  uint32_t cup = 0;
    // producer counters for kchunk = ki+2: slot ps, use index pu
    int ps = 2;  int pu = 0;

    for (int ki = 0; ki < NK; ki++) {
        const int kc = ki + 2;
        if (kc < NK) {
            if (pu >= 1)
                mbar_wait(mbE + (uint32_t)ps * 16u, (uint32_t)((pu - 1) & 1));
            produce(kc, ps);
            if (++ps == NSTAGE) { ps = 0; pu++; }
        }

        mbar_wait(mbF + (uint32_t)cs * 16u, cup);

        const uint32_t aBase = sb + (uint32_t)cs * STAGE_BYTES;
        const uint32_t bBase = aBase + 16384u;

        #pragma unroll
        for (int ks = 0; ks < 4; ks++) {          // four k16 steps in BK=64
            const uint32_t ch = (uint32_t)(((ks * 2 + kc_lane) ^ l7) << 4);
            uint32_t af[4][4], bf[2][4];
            const uint32_t aAddr = aBase + arowbase + ch;
            ldm_x4(af[0], aAddr);
            ldm_x4(af[1], aAddr + 2048u);
            ldm_x4(af[2], aAddr + 4096u);
            ldm_x4(af[3], aAddr + 6144u);
            const uint32_t bAddr = bBase + browbase + ch;
            ldm_x4(bf[0], bAddr);
            ldm_x4(bf[1], bAddr + 2048u);
            #pragma unroll
            for (int mt = 0; mt < 4; mt++) {
                #pragma unroll
                for (int nt = 0; nt < 4; nt++) {
                    const int ng = nt >> 1, hh = nt & 1;
                    mma_bf16(acc[mt][nt], af[mt], bf[ng][hh], bf[ng][hh + 2]);
                }
            }
        }

        __syncwarp();
        if (lane == 0) mbar_arrive(mbE + (uint32_t)cs * 16u);
        if (++cs == NSTAGE) { cs = 0; cup ^= 1; }
    }

    __syncthreads();   // sbias visibility + all warps done before smem reuse

    // ---- epilogue: bias, target capture, per-row (m,s) --------------------
    const int g  = lane >> 2;
    const int tc = lane & 3;

    float bv[4][2];
    #pragma unroll
    for (int nt = 0; nt < 4; nt++) {
        const int cl = wn * 32 + nt * 8 + tc * 2;
        bv[nt][0] = sbias[cl];
        bv[nt][1] = sbias[cl + 1];
    }

    float* spm = (float*)(smem + OFF_PM);   // [4][128]
    float* sps = (float*)(smem + OFF_PS);

    #pragma unroll
    for (int mt = 0; mt < 4; mt++) {
        #pragma unroll
        for (int hh = 0; hh < 2; hh++) {
            const int rloc = wm * 64 + mt * 16 + g + 8 * hh;
            const int t = row0 + rloc;
            const long long tg = load_target(target_raw, t);

            float v[8];
            float m = -INFINITY;
            #pragma unroll
            for (int nt = 0; nt < 4; nt++) {
                #pragma unroll
                for (int cc = 0; cc < 2; cc++) {
                    const float val = acc[mt][nt][hh * 2 + cc] + bv[nt][cc];
                    v[nt * 2 + cc] = val;
                    m = fmaxf(m, val);
                    const long long cg = (long long)(col0 + wn * 32 + nt * 8 + tc * 2 + cc);
                    if (cg == tg) g_tgt[t] = val;
                }
            }
            float s = 0.0f;
            #pragma unroll
            for (int j = 0; j < 8; j++)
                s += __expf(v[j] - m);

            // reduce across the 4 lanes of the quad (same row)
            #pragma unroll
            for (int off = 1; off <= 2; off <<= 1) {
                float m2 = __shfl_xor_sync(0xffffffffu, m, off);
                float s2 = __shfl_xor_sync(0xffffffffu, s, off);
                float mn = fmaxf(m, m2);
                s = s * __expf(m - mn) + s2 * __expf(m2 - mn);
                m = mn;
            }
            if (tc == 0) {
                spm[wn * 128 + rloc] = m;
                sps[wn * 128 + rloc] = s;
            }
        }
    }
    __syncthreads();

    // merge 4 warp-column partials per row -> global partials
    if (tid < 128) {
        float m = spm[tid], s = sps[tid];
        #pragma unroll
        for (int w = 1; w < 4; w++) {
            float m2 = spm[w * 128 + tid];
            float s2 = sps[w * 128 + tid];
            float mn = fmaxf(m, m2);
            s = s * __expf(m - mn) + s2 * __expf(m2 - mn);
            m = mn;
        }
        g_pm[chnk * BT + row0 + tid] = m;
        g_ps[chnk * BT + row0 + tid] = s;
    }
}

// ------------------------- stage 2: merge + reduce --------------------------
__global__ __launch_bounds__(256)
void reduce_kernel(const void* __restrict__ target_raw)
{
    const int t = blockIdx.x * blockDim.x + threadIdx.x;

    float m = -INFINITY, s = 0.0f;
    for (int c = 0; c < NCH; c++) {
        float mc = g_pm[c * BT + t];
        float sc = g_ps[c * BT + t];
        float mn = fmaxf(m, mc);
        s = s * expf(m - mn) + sc * expf(mc - mn);
        m = mn;
    }
    const float lse = m + logf(s);

    const long long tg = load_target(target_raw, t);
    const int valid = (tg != (long long)IGNORE_INDEX) ? 1 : 0;
    float per = valid ? (lse - g_tgt[t]) : 0.0f;

    #pragma unroll
    for (int off = 16; off >= 1; off >>= 1)
        per += __shfl_xor_sync(0xffffffffu, per, off);
    int vc = valid;
    #pragma unroll
    for (int off = 16; off >= 1; off >>= 1)
        vc += __shfl_xor_sync(0xffffffffu, vc, off);
    if ((threadIdx.x & 31) == 0) {
        atomicAdd(&g_sum, per);
        atomicAdd(&g_cnt, vc);
    }
}

__global__ void finalize_kernel(float* __restrict__ out)
{
    int c = g_cnt;
    if (c < 1) c = 1;
    out[0] = g_sum / (float)c;
}

// ------------------------- host launch --------------------------------------
extern "C" void kernel_launch(void* const* d_in, const int* in_sizes, int n_in,
                              void* d_out, int out_size)
{
    const float* x          = (const float*)d_in[0];
    const void*  target_raw = d_in[1];
    const float* w          = (const float*)d_in[2];
    const float* bias       = (const float*)d_in[3];
    float*       out        = (float*)d_out;

    cudaFuncSetAttribute(gemm_kernel, cudaFuncAttributeMaxDynamicSharedMemorySize,
                         SMEM_DYN);

    void *xb = nullptr, *wb = nullptr;
    cudaGetSymbolAddress(&xb, g_xb);
    cudaGetSymbolAddress(&wb, g_wb);

    {
        int n8 = (BT * H) / 8;
        convert_kernel<<<(n8 + 255) / 256, 256>>>(x, (__nv_bfloat16*)xb, n8);
    }
    {
        int n8 = (int)(((size_t)V * H) / 8);
        convert_kernel<<<(n8 + 255) / 256, 256>>>(w, (__nv_bfloat16*)wb, n8);
    }

    init_kernel<<<1, 256>>>(target_raw);

    dim3 grid(NTR, NCH);
    gemm_kernel<<<grid, 256, SMEM_DYN>>>(target_raw, bias);

    reduce_kernel<<<BT / 256, 256>>>(target_raw);
    finalize_kernel<<<1, 1>>>(out);
}